// round 13
// baseline (speedup 1.0000x reference)
#include <cuda_runtime.h>

// EntmaxBisect: alpha=1.5, 50-iter bisection over last dim (4096), rows = 16384.
//
// Math: with p = 1/4095 every positive (Xs_i - t)^p lies in (0.975, 1], so
// sum(Z) >= 1 <=> count(Xs > t) >= 2 <=> second_largest(Xs) > t. Bisection
// depends only on the row top-2, replicated bit-exactly on the reference fp32
// lattice; fully unrolled branch-free (iterations past convergence are exact
// no-ops, so 50 iters == reference bit-for-bit).
//
// Structure (R11-proven: register prefetch beats bulk-DMA ring, R12 lesson):
// persistent CTAs (608 = 4/SM x 152 SM), prefetch for row i+1 issued at the
// TOP of iteration i, consumed at rotation. Bisect in warp 0 only. One-time
// startup stagger de-phases the 4 co-resident CTAs per SM. Sparsity guard:
// thread whose own max is below t skips pow/normalize (~99.6% of threads);
// inactive threads store their zeros EARLY (before the sum barrier) so the
// store stream overlaps the reduce instead of trailing it.

#define D        4096
#define THREADS  512
#define NWARPS   16
#define N_ITER   50
#define GRID     608
#define NSM      152
#define STAGGER  1550u

__global__ __launch_bounds__(THREADS, 4)
void entmax_bisect_kernel(const float* __restrict__ X, float* __restrict__ out,
                          int nrows)
{
    const int tid  = threadIdx.x;
    const int lane = tid & 31;
    const int wid  = tid >> 5;

    __shared__ float sm1[NWARPS];
    __shared__ float sm2[NWARPS];
    __shared__ alignas(16) float ssum[NWARPS];
    __shared__ float sbc;

    const float4* __restrict__ x4 = reinterpret_cast<const float4*>(X);
    float4* __restrict__ o4 = reinterpret_cast<float4*>(out);

    int row = blockIdx.x;
    if (row >= nrows) return;

    // ---- one-time de-phasing of the 4 co-resident CTAs on each SM ----
    {
        unsigned q = (unsigned)(blockIdx.x / NSM) & 3u;
        if (q) {
            unsigned long long tgt = clock64() + (unsigned long long)q * STAGGER;
            while (clock64() < tgt) { }
        }
    }

    size_t base = (size_t)row * (D / 4);
    float4 v0 = x4[base + tid];
    float4 v1 = x4[base + tid + THREADS];

    while (true) {
        const int  nrow = row + GRID;
        const bool more = (nrow < nrows);
        // ---- prefetch next row NOW; consumed only at the end-of-iter rotate
        const size_t pb = (size_t)(more ? nrow : row) * (D / 4);
        float4 nv0 = x4[pb + tid];
        float4 nv1 = x4[pb + tid + THREADS];

        // ---- per-thread top-2 of raw X: two independent chains, merged ----
        float a1, a2;
        {
            float m1a = fmaxf(v0.x, v0.y), lo;
            float m2a = fminf(v0.x, v0.y);
            lo = fminf(m1a, v0.z); m1a = fmaxf(m1a, v0.z); m2a = fmaxf(m2a, lo);
            lo = fminf(m1a, v0.w); m1a = fmaxf(m1a, v0.w); m2a = fmaxf(m2a, lo);
            float m1b = fmaxf(v1.x, v1.y);
            float m2b = fminf(v1.x, v1.y);
            lo = fminf(m1b, v1.z); m1b = fmaxf(m1b, v1.z); m2b = fmaxf(m2b, lo);
            lo = fminf(m1b, v1.w); m1b = fmaxf(m1b, v1.w); m2b = fmaxf(m2b, lo);
            a1 = fmaxf(m1a, m1b);
            a2 = fmaxf(fminf(m1a, m1b), fmaxf(m2a, m2b));
        }

        // ---- warp top-2 reduce ----
        float w1 = a1, w2 = a2;
        #pragma unroll
        for (int off = 16; off > 0; off >>= 1) {
            float b1 = __shfl_down_sync(0xffffffffu, w1, off);
            float b2 = __shfl_down_sync(0xffffffffu, w2, off);
            float lo = fminf(w1, b1);
            w1 = fmaxf(w1, b1);
            w2 = fmaxf(fmaxf(w2, b2), lo);
        }
        if (lane == 0) { sm1[wid] = w1; sm2[wid] = w2; }
        __syncthreads();                                    // sync1

        // ---- warp 0 ONLY: combine 16 partials + branchless unrolled bisect
        if (wid == 0) {
            float M = sm1[lane & (NWARPS - 1)];
            float S = sm2[lane & (NWARPS - 1)];
            #pragma unroll
            for (int off = 8; off > 0; off >>= 1) {
                float b1 = __shfl_xor_sync(0xffffffffu, M, off);
                float b2 = __shfl_xor_sync(0xffffffffu, S, off);
                float lo = fminf(M, b1);
                M = fmaxf(M, b1);
                S = fmaxf(fmaxf(S, b2), lo);
            }
            M *= 0.5f;                       // exact: top-2 of Xs = 0.5*top-2 of X
            S *= 0.5f;
            // bit-faithful fp32 bisection, fully unrolled, branch-free
            float tmin = M - 1.0f;
            float diff = (M - 0.015625f) - tmin;   // tmax - tmin
            float t = tmin;
            #pragma unroll
            for (int i = 0; i < N_ITER; i++) {
                diff = diff * 0.5f;          // exact, independent chain
                t = tmin + diff;
                tmin = (S > t) ? t : tmin;   // FSEL, no branch
            }
            if (lane == 0) sbc = t;          // final tested t == reference's
        }
        __syncthreads();                                    // sync2

        const float t = sbc;
        const float p = 1.0f / 4095.0f;      // == fp32(1/(d-1))
        const size_t ob = (size_t)row * (D / 4);

        // ---- sparsity split ----
        const bool active = (fmaf(0.5f, a1, -t) > 0.0f);

        // inactive threads: store zeros NOW (overlaps reduce + sync3)
        if (!active) {
            const float4 zr = make_float4(0.0f, 0.0f, 0.0f, 0.0f);
            __stcs(&o4[ob + tid], zr);
            __stcs(&o4[ob + tid + THREADS], zr);
        }

        // ---- Z phase (active threads only, in place over v regs) ----
        float lsum = 0.0f;
        if (active) {                         // ~1-2 threads per row of 512
            float u;
            u = fmaf(0.5f, v0.x, -t); v0.x = (u > 0.0f) ? __powf(u, p) : 0.0f; lsum += v0.x;
            u = fmaf(0.5f, v0.y, -t); v0.y = (u > 0.0f) ? __powf(u, p) : 0.0f; lsum += v0.y;
            u = fmaf(0.5f, v0.z, -t); v0.z = (u > 0.0f) ? __powf(u, p) : 0.0f; lsum += v0.z;
            u = fmaf(0.5f, v0.w, -t); v0.w = (u > 0.0f) ? __powf(u, p) : 0.0f; lsum += v0.w;
            u = fmaf(0.5f, v1.x, -t); v1.x = (u > 0.0f) ? __powf(u, p) : 0.0f; lsum += v1.x;
            u = fmaf(0.5f, v1.y, -t); v1.y = (u > 0.0f) ? __powf(u, p) : 0.0f; lsum += v1.y;
            u = fmaf(0.5f, v1.z, -t); v1.z = (u > 0.0f) ? __powf(u, p) : 0.0f; lsum += v1.z;
            u = fmaf(0.5f, v1.w, -t); v1.w = (u > 0.0f) ? __powf(u, p) : 0.0f; lsum += v1.w;
        }
        // warps with no active lane skip the shuffle reduce entirely
        if (__any_sync(0xffffffffu, active)) {
            #pragma unroll
            for (int off = 16; off > 0; off >>= 1)
                lsum += __shfl_down_sync(0xffffffffu, lsum, off);
            if (lane == 0) ssum[wid] = lsum;
        } else {
            if (lane == 0) ssum[wid] = 0.0f;
        }
        __syncthreads();                                    // sync3

        // ---- active threads: normalize + store ----
        if (active) {
            const float4* s4 = reinterpret_cast<const float4*>(ssum);
            float4 A = s4[0], B = s4[1], C = s4[2], E = s4[3];
            float tot = ((A.x + A.y) + (A.z + A.w)) + ((B.x + B.y) + (B.z + B.w))
                      + ((C.x + C.y) + (C.z + C.w)) + ((E.x + E.y) + (E.z + E.w));
            const float inv = 1.0f / tot;
            float4 r0, r1;
            r0.x = v0.x * inv; r0.y = v0.y * inv; r0.z = v0.z * inv; r0.w = v0.w * inv;
            r1.x = v1.x * inv; r1.y = v1.y * inv; r1.z = v1.z * inv; r1.w = v1.w * inv;
            __stcs(&o4[ob + tid], r0);
            __stcs(&o4[ob + tid + THREADS], r1);
        }

        if (!more) break;
        v0 = nv0; v1 = nv1;                   // consume prefetch (full-iter distance)
        row = nrow;
    }
}

extern "C" void kernel_launch(void* const* d_in, const int* in_sizes, int n_in,
                              void* d_out, int out_size)
{
    const float* X = (const float*)d_in[0];
    float* out = (float*)d_out;
    const int n = in_sizes[0];          // 8*2048*4096
    const int rows = n / D;             // 16384
    entmax_bisect_kernel<<<GRID, THREADS>>>(X, out, rows);
}

// round 14
// speedup vs baseline: 1.0950x; 1.0950x over previous
#include <cuda_runtime.h>

// EntmaxBisect: alpha=1.5, 50-iter bisection over last dim (4096), rows = 16384.
//
// Math: with p = 1/4095 every positive (Xs_i - t)^p lies in (0.975, 1], so
// sum(Z) >= 1 <=> count(Xs > t) >= 2 <=> second_largest(Xs) > t. Bisection
// depends only on the row top-2, replicated bit-exactly on the reference fp32
// lattice. The 50-iter loop is fully unrolled and branch-free: the diff-halving
// ladder is exact fp32 and forms an independent chain; iterations past
// convergence are arithmetic no-ops, so 50 iters == reference bit-for-bit.
//
// Structure (best measured: ncu 83.4us, DRAM 72.7%): persistent CTAs
// (608 = 4/SM x 152 SM), register prefetch for row i+1 issued at the TOP of
// iteration i, consumed at rotation (full-iteration distance). Bisect in
// warp 0 only. One-time startup stagger de-phases the 4 co-resident CTAs per
// SM. Sparsity guard: thread whose own max is below t skips pow/normalize
// (~99.6% of threads). Uniform convergent store tail (R13 lesson: splitting
// stores by activity wrecks coalescing and barrier overlap).

#define D        4096
#define THREADS  512
#define NWARPS   16
#define N_ITER   50
#define GRID     608
#define NSM      152
#define STAGGER  1550u

__device__ __forceinline__ void thread_top2(const float4& a, const float4& b,
                                            float& m1, float& m2)
{
    m1 = __int_as_float(0xff800000);   // -inf
    m2 = m1;
    float v, lo;
    v = a.x; lo = fminf(m1, v); m1 = fmaxf(m1, v); m2 = fmaxf(m2, lo);
    v = a.y; lo = fminf(m1, v); m1 = fmaxf(m1, v); m2 = fmaxf(m2, lo);
    v = a.z; lo = fminf(m1, v); m1 = fmaxf(m1, v); m2 = fmaxf(m2, lo);
    v = a.w; lo = fminf(m1, v); m1 = fmaxf(m1, v); m2 = fmaxf(m2, lo);
    v = b.x; lo = fminf(m1, v); m1 = fmaxf(m1, v); m2 = fmaxf(m2, lo);
    v = b.y; lo = fminf(m1, v); m1 = fmaxf(m1, v); m2 = fmaxf(m2, lo);
    v = b.z; lo = fminf(m1, v); m1 = fmaxf(m1, v); m2 = fmaxf(m2, lo);
    v = b.w; lo = fminf(m1, v); m1 = fmaxf(m1, v); m2 = fmaxf(m2, lo);
}

__global__ __launch_bounds__(THREADS, 4)
void entmax_bisect_kernel(const float* __restrict__ X, float* __restrict__ out,
                          int nrows)
{
    const int tid  = threadIdx.x;
    const int lane = tid & 31;
    const int wid  = tid >> 5;

    __shared__ float sm1[NWARPS];
    __shared__ float sm2[NWARPS];
    __shared__ alignas(16) float ssum[NWARPS];
    __shared__ float sbc;

    const float4* __restrict__ x4 = reinterpret_cast<const float4*>(X);
    float4* __restrict__ o4 = reinterpret_cast<float4*>(out);

    int row = blockIdx.x;
    if (row >= nrows) return;

    // ---- one-time de-phasing of the 4 co-resident CTAs on each SM ----
    {
        unsigned q = (unsigned)(blockIdx.x / NSM) & 3u;
        if (q) {
            unsigned long long tgt = clock64() + (unsigned long long)q * STAGGER;
            while (clock64() < tgt) { }
        }
    }

    size_t base = (size_t)row * (D / 4);
    float4 v0 = x4[base + tid];
    float4 v1 = x4[base + tid + THREADS];

    while (true) {
        const int  nrow = row + GRID;
        const bool more = (nrow < nrows);
        // ---- prefetch next row NOW; consumed only at the end-of-iter rotate
        const size_t pb = (size_t)(more ? nrow : row) * (D / 4);
        float4 nv0 = x4[pb + tid];
        float4 nv1 = x4[pb + tid + THREADS];

        // ---- per-thread top-2 of raw X (a1 kept as sparsity guard) ----
        float a1, a2;
        thread_top2(v0, v1, a1, a2);

        // ---- warp top-2 reduce ----
        float w1 = a1, w2 = a2;
        #pragma unroll
        for (int off = 16; off > 0; off >>= 1) {
            float b1 = __shfl_down_sync(0xffffffffu, w1, off);
            float b2 = __shfl_down_sync(0xffffffffu, w2, off);
            float lo = fminf(w1, b1);
            w1 = fmaxf(w1, b1);
            w2 = fmaxf(fmaxf(w2, b2), lo);
        }
        if (lane == 0) { sm1[wid] = w1; sm2[wid] = w2; }
        __syncthreads();                                    // sync1

        // ---- warp 0 ONLY: combine 16 partials + branchless unrolled bisect
        if (wid == 0) {
            float M = sm1[lane & (NWARPS - 1)];
            float S = sm2[lane & (NWARPS - 1)];
            #pragma unroll
            for (int off = 8; off > 0; off >>= 1) {
                float b1 = __shfl_xor_sync(0xffffffffu, M, off);
                float b2 = __shfl_xor_sync(0xffffffffu, S, off);
                float lo = fminf(M, b1);
                M = fmaxf(M, b1);
                S = fmaxf(fmaxf(S, b2), lo);
            }
            M *= 0.5f;                       // exact: top-2 of Xs = 0.5*top-2 of X
            S *= 0.5f;
            // bit-faithful fp32 bisection, fully unrolled, branch-free.
            float tmin = M - 1.0f;
            float diff = (M - 0.015625f) - tmin;   // tmax - tmin
            float t = tmin;
            #pragma unroll
            for (int i = 0; i < N_ITER; i++) {
                diff = diff * 0.5f;          // exact, independent chain
                t = tmin + diff;
                tmin = (S > t) ? t : tmin;   // FSETP/FSEL, no branch
            }
            if (lane == 0) sbc = t;          // final tested t == reference's
        }
        __syncthreads();                                    // sync2

        const float t = sbc;
        const float p = 1.0f / 4095.0f;      // == fp32(1/(d-1))

        // ---- Z phase (sparsity-guarded, in place over v regs) ----
        const bool active = (fmaf(0.5f, a1, -t) > 0.0f);
        float lsum = 0.0f;
        if (active) {                         // ~1-2 threads per row of 512
            float u;
            u = fmaf(0.5f, v0.x, -t); v0.x = (u > 0.0f) ? __powf(u, p) : 0.0f; lsum += v0.x;
            u = fmaf(0.5f, v0.y, -t); v0.y = (u > 0.0f) ? __powf(u, p) : 0.0f; lsum += v0.y;
            u = fmaf(0.5f, v0.z, -t); v0.z = (u > 0.0f) ? __powf(u, p) : 0.0f; lsum += v0.z;
            u = fmaf(0.5f, v0.w, -t); v0.w = (u > 0.0f) ? __powf(u, p) : 0.0f; lsum += v0.w;
            u = fmaf(0.5f, v1.x, -t); v1.x = (u > 0.0f) ? __powf(u, p) : 0.0f; lsum += v1.x;
            u = fmaf(0.5f, v1.y, -t); v1.y = (u > 0.0f) ? __powf(u, p) : 0.0f; lsum += v1.y;
            u = fmaf(0.5f, v1.z, -t); v1.z = (u > 0.0f) ? __powf(u, p) : 0.0f; lsum += v1.z;
            u = fmaf(0.5f, v1.w, -t); v1.w = (u > 0.0f) ? __powf(u, p) : 0.0f; lsum += v1.w;
        }
        #pragma unroll
        for (int off = 16; off > 0; off >>= 1)
            lsum += __shfl_down_sync(0xffffffffu, lsum, off);
        if (lane == 0) ssum[wid] = lsum;
        __syncthreads();                                    // sync3

        // ---- normalize + store (uniform, convergent tail) ----
        const size_t ob = (size_t)row * (D / 4);
        if (active) {
            const float4* s4 = reinterpret_cast<const float4*>(ssum);
            float4 A = s4[0], B = s4[1], C = s4[2], E = s4[3];
            float tot = ((A.x + A.y) + (A.z + A.w)) + ((B.x + B.y) + (B.z + B.w))
                      + ((C.x + C.y) + (C.z + C.w)) + ((E.x + E.y) + (E.z + E.w));
            const float inv = 1.0f / tot;
            float4 r0, r1;
            r0.x = v0.x * inv; r0.y = v0.y * inv; r0.z = v0.z * inv; r0.w = v0.w * inv;
            r1.x = v1.x * inv; r1.y = v1.y * inv; r1.z = v1.z * inv; r1.w = v1.w * inv;
            __stcs(&o4[ob + tid], r0);
            __stcs(&o4[ob + tid + THREADS], r1);
        } else {
            const float4 zr = make_float4(0.0f, 0.0f, 0.0f, 0.0f);
            __stcs(&o4[ob + tid], zr);
            __stcs(&o4[ob + tid + THREADS], zr);
        }

        if (!more) break;
        v0 = nv0; v1 = nv1;                   // consume prefetch (full-iter distance)
        row = nrow;
    }
}

extern "C" void kernel_launch(void* const* d_in, const int* in_sizes, int n_in,
                              void* d_out, int out_size)
{
    const float* X = (const float*)d_in[0];
    float* out = (float*)d_out;
    const int n = in_sizes[0];          // 8*2048*4096
    const int rows = n / D;             // 16384
    entmax_bisect_kernel<<<GRID, THREADS>>>(X, out, rows);
}